// round 2
// baseline (speedup 1.0000x reference)
#include <cuda_runtime.h>
#include <float.h>
#include <math.h>

// Problem geometry
#define HH 512
#define WW 512
#define SLICES 128                 // B*P = 64*2
#define NB 32                      // blocks per slice
#define TPB 256                    // threads per block
#define ELEMS_PER_SLICE (HH*WW)    // 262144
#define ELEMS_PER_BLOCK (ELEMS_PER_SLICE/NB)   // 8192
#define VEC4_PER_BLOCK  (ELEMS_PER_BLOCK/4)    // 2048
#define VEC4_PER_THREAD (VEC4_PER_BLOCK/TPB)   // 8

// Per-block partials (static device scratch; no allocation)
__device__ float g_s [SLICES*NB];
__device__ float g_sx[SLICES*NB];
__device__ float g_sy[SLICES*NB];
__device__ float g_tv[SLICES*NB];
__device__ int   g_ti[SLICES*NB];

__global__ __launch_bounds__(TPB)
void dsnt_pass1(const float4* __restrict__ inp, const float4* __restrict__ tgt)
{
    const int blk   = blockIdx.x;          // 0..SLICES*NB-1
    const int slice = blk >> 5;            // /NB
    const int sub   = blk & (NB-1);
    const int tid   = threadIdx.x;

    const int slice_base4 = slice * (ELEMS_PER_SLICE/4);
    const int chunk_base4 = sub * VEC4_PER_BLOCK;

    float s = 0.f, sx = 0.f, sy = 0.f;
    float tv = -FLT_MAX;
    int   ti = 0x7fffffff;

#pragma unroll
    for (int k = 0; k < VEC4_PER_THREAD; k++) {
        const int local4 = k * TPB + tid;               // block-stride, coalesced
        const int g4     = slice_base4 + chunk_base4 + local4;
        const float4 v = inp[g4];
        const float4 t = tgt[g4];

        const int ei  = (chunk_base4 + local4) << 2;    // element index in slice
        const int row = ei >> 9;                        // /512
        const int col = ei & 511;

        const float e0 = __expf(v.x);
        const float e1 = __expf(v.y);
        const float e2 = __expf(v.z);
        const float e3 = __expf(v.w);
        const float es = (e0 + e1) + (e2 + e3);
        s  += es;
        sx += e0*(float)(col+1) + e1*(float)(col+2)
            + e2*(float)(col+3) + e3*(float)(col+4);
        sy += es * (float)(row+1);

        // target running argmax (indices visited in increasing order per thread)
        if (t.x > tv) { tv = t.x; ti = ei;     }
        if (t.y > tv) { tv = t.y; ti = ei + 1; }
        if (t.z > tv) { tv = t.z; ti = ei + 2; }
        if (t.w > tv) { tv = t.w; ti = ei + 3; }
    }

    // ---- warp reduce ----
#pragma unroll
    for (int off = 16; off > 0; off >>= 1) {
        s  += __shfl_down_sync(0xffffffffu, s,  off);
        sx += __shfl_down_sync(0xffffffffu, sx, off);
        sy += __shfl_down_sync(0xffffffffu, sy, off);
        float ov = __shfl_down_sync(0xffffffffu, tv, off);
        int   oi = __shfl_down_sync(0xffffffffu, ti, off);
        if (ov > tv || (ov == tv && oi < ti)) { tv = ov; ti = oi; }
    }

    __shared__ float sh_s[8], sh_sx[8], sh_sy[8], sh_tv[8];
    __shared__ int   sh_ti[8];
    const int wid = tid >> 5;
    const int lid = tid & 31;
    if (lid == 0) { sh_s[wid]=s; sh_sx[wid]=sx; sh_sy[wid]=sy; sh_tv[wid]=tv; sh_ti[wid]=ti; }
    __syncthreads();

    if (wid == 0) {
        s  = (lid < 8) ? sh_s [lid] : 0.f;
        sx = (lid < 8) ? sh_sx[lid] : 0.f;
        sy = (lid < 8) ? sh_sy[lid] : 0.f;
        tv = (lid < 8) ? sh_tv[lid] : -FLT_MAX;
        ti = (lid < 8) ? sh_ti[lid] : 0x7fffffff;
#pragma unroll
        for (int off = 4; off > 0; off >>= 1) {
            s  += __shfl_down_sync(0xffffffffu, s,  off);
            sx += __shfl_down_sync(0xffffffffu, sx, off);
            sy += __shfl_down_sync(0xffffffffu, sy, off);
            float ov = __shfl_down_sync(0xffffffffu, tv, off);
            int   oi = __shfl_down_sync(0xffffffffu, ti, off);
            if (ov > tv || (ov == tv && oi < ti)) { tv = ov; ti = oi; }
        }
        if (lid == 0) {
            g_s [blk] = s;
            g_sx[blk] = sx;
            g_sy[blk] = sy;
            g_tv[blk] = tv;
            g_ti[blk] = ti;
        }
    }
}

__global__ __launch_bounds__(128)
void dsnt_pass2(float* __restrict__ out)
{
    __shared__ float px[SLICES], py[SLICES], txs[SLICES], tys[SLICES];
    __shared__ double red[64];

    const int t = threadIdx.x;

    // combine the NB partials for slice t (fp64 to kill summation-order noise)
    {
        double S = 0.0, SX = 0.0, SY = 0.0;
        float tv = -FLT_MAX; int ti = 0x7fffffff;
#pragma unroll
        for (int j = 0; j < NB; j++) {
            const int id = t * NB + j;
            S  += (double)g_s [id];
            SX += (double)g_sx[id];
            SY += (double)g_sy[id];
            float v = g_tv[id]; int i = g_ti[id];
            if (v > tv || (v == tv && i < ti)) { tv = v; ti = i; }
        }
        px[t]  = (float)(SX / (S * 512.0));
        py[t]  = (float)(SY / (S * 512.0));
        txs[t] = (float)((ti & 511) + 1) * (1.0f / 512.0f);
        tys[t] = (float)((ti >> 9)  + 1) * (1.0f / 512.0f);
    }
    __syncthreads();

    if (t < 64) {
        const int p0 = 2 * t, p1 = 2 * t + 1;
        const double dx0 = (double)txs[p0] - (double)px[p0];
        const double dy0 = (double)tys[p0] - (double)py[p0];
        const double dx1 = (double)txs[p1] - (double)px[p1];
        const double dy1 = (double)tys[p1] - (double)py[p1];
        const double ed  = sqrt(dx0*dx0 + dy0*dy0) + sqrt(dx1*dx1 + dy1*dy1);

        const double pvx = (double)px[p0] - (double)px[p1];
        const double pvy = (double)py[p0] - (double)py[p1];
        const double tvx = (double)txs[p0] - (double)txs[p1];
        const double tvy = (double)tys[p0] - (double)tys[p1];
        const double pd  = sqrt(pvx*pvx + pvy*pvy);
        const double td  = sqrt(tvx*tvx + tvy*tvy);
        const double dot = pvx*tvx + pvy*tvy;

        red[t] = ed + fabs(pd - td) + (1.0 - cos(dot / (pd * td)));
    }
    __syncthreads();

    if (t == 0) {
        double acc = 0.0;
#pragma unroll
        for (int i = 0; i < 64; i++) acc += red[i];
        out[0] = (float)(acc / 64.0);
    }
}

extern "C" void kernel_launch(void* const* d_in, const int* in_sizes, int n_in,
                              void* d_out, int out_size)
{
    const float4* inp = (const float4*)d_in[0];
    const float4* tgt = (const float4*)d_in[1];
    float* out = (float*)d_out;

    dsnt_pass1<<<SLICES * NB, TPB>>>(inp, tgt);
    dsnt_pass2<<<1, 128>>>(out);
}